// round 5
// baseline (speedup 1.0000x reference)
#include <cuda_runtime.h>
#include <cuda_bf16.h>
#include <cstdint>

#define NN 4096
#define BB 512
#define DTc 0.1f

// GEMM tiling (mma.sync bf16)
#define BM 128
#define BN 128
#define BKt 32
#define NKT (NN / BKt)        // 128 k-tile iterations
#define ROWB 80               // padded smem row bytes (64B data + 16B pad)
#define TILEB (128 * ROWB)    // 10240 bytes per operand tile
#define STAGEB (4 * TILEB)    // Ahi, Alo, Bhi, Blo = 40960
#define NSTG 4
#define SMEM_BYTES (NSTG * STAGEB)   // 163840 (epilogue reuses 67584 of it)

// --------------------------------------------------------------------------
// Device scratch (no allocation allowed)
// --------------------------------------------------------------------------
__device__ __align__(256) __nv_bfloat16 g_Ahi[(size_t)NN * NN];    // 32 MB
__device__ __align__(256) __nv_bfloat16 g_Alo[(size_t)NN * NN];    // 32 MB
__device__ __align__(256) __nv_bfloat16 g_Bhi[2][(size_t)BB * NN]; // 2x4 MB
__device__ __align__(256) __nv_bfloat16 g_Blo[2][(size_t)BB * NN]; // 2x4 MB
__device__ float g_x[2][2 * BB];
__device__ float g_zha[2][BB];     // ping-pong Z.h accumulators

// --------------------------------------------------------------------------
// Helpers
// --------------------------------------------------------------------------
__device__ __forceinline__ uint32_t smem_u32(const void* p) {
    return (uint32_t)__cvta_generic_to_shared((void*)p);
}

__device__ __forceinline__ void cp16(uint32_t dst, const void* src) {
    asm volatile("cp.async.cg.shared.global [%0], [%1], 16;" :: "r"(dst), "l"(src) : "memory");
}

__device__ __forceinline__ void ldsm4(uint32_t* r, uint32_t a) {
    asm volatile("ldmatrix.sync.aligned.m8n8.x4.shared.b16 {%0,%1,%2,%3}, [%4];"
                 : "=r"(r[0]), "=r"(r[1]), "=r"(r[2]), "=r"(r[3]) : "r"(a));
}

__device__ __forceinline__ void ldsm2(uint32_t* r, uint32_t a) {
    asm volatile("ldmatrix.sync.aligned.m8n8.x2.shared.b16 {%0,%1}, [%2];"
                 : "=r"(r[0]), "=r"(r[1]) : "r"(a));
}

// NOTE: not volatile — pure register op; lets ptxas interleave HMMA with LDSM issue.
__device__ __forceinline__ void mma_bf16(float* d, const uint32_t* a, const uint32_t* b) {
    asm("mma.sync.aligned.m16n8k16.row.col.f32.bf16.bf16.f32 "
        "{%0,%1,%2,%3}, {%4,%5,%6,%7}, {%8,%9}, {%0,%1,%2,%3};"
        : "+f"(d[0]), "+f"(d[1]), "+f"(d[2]), "+f"(d[3])
        : "r"(a[0]), "r"(a[1]), "r"(a[2]), "r"(a[3]), "r"(b[0]), "r"(b[1]));
}

// --------------------------------------------------------------------------
// Build A_hi/A_lo (bf16 split of P22); also zeroes the zh accumulators.
// --------------------------------------------------------------------------
__global__ void build_split_kernel(const float* __restrict__ W,
                                   const float* __restrict__ U,
                                   const float* __restrict__ V,
                                   const float* __restrict__ Mv,
                                   const float* __restrict__ Z,
                                   const float* __restrict__ Cc,
                                   const float* __restrict__ Bm) {
    if (blockIdx.x == 0 && blockIdx.y == 0) {
        int tIdx = threadIdx.x;
        g_zha[0][tIdx] = 0.f;       g_zha[1][tIdx] = 0.f;
        g_zha[0][tIdx + 256] = 0.f; g_zha[1][tIdx + 256] = 0.f;
    }
    int i = blockIdx.y;
    int j = (blockIdx.x * blockDim.x + threadIdx.x) * 4;
    float cb = Cc[0] * Bm[0] + Cc[1] * Bm[1];
    float mi = Mv[i];
    float u0 = U[i * 4 + 0], u1 = U[i * 4 + 1], u2 = U[i * 4 + 2], u3 = U[i * 4 + 3];
    float4 w = *(const float4*)(W + (size_t)i * NN + j);
    const float* wp = &w.x;
    union { __nv_bfloat16 h[4]; uint2 u; } ph, pl;
#pragma unroll
    for (int jj = 0; jj < 4; ++jj) {
        int jc = j + jj;
        float4 vv = *(const float4*)(V + (size_t)jc * 4);
        float uv = u0 * vv.x + u1 * vv.y + u2 * vv.z + u3 * vv.w;
        float val = DTc * (wp[jj] + uv) + cb * mi * Z[jc];
        if (jc == i) val += 1.0f - DTc;
        __nv_bfloat16 hi = __float2bfloat16(val);
        ph.h[jj] = hi;
        pl.h[jj] = __float2bfloat16(val - __bfloat162float(hi));
    }
    *(uint2*)(g_Ahi + (size_t)i * NN + j) = ph.u;
    *(uint2*)(g_Alo + (size_t)i * NN + j) = pl.u;
}

// --------------------------------------------------------------------------
// init_all: h0 -> traj_0 h-block + transposed bf16 split Bhi/Blo[0]
//           + zh0 accumulation + x init (block 0)
// grid (NN/32, BB/32), block (32,8)
// --------------------------------------------------------------------------
__global__ void init_all_kernel(const float* __restrict__ h0,
                                const float* __restrict__ x0,
                                const float* __restrict__ x1,
                                const float* __restrict__ Z,
                                float* __restrict__ traj0h) {
    __shared__ float t[32][33];
    __shared__ float zs[8][33];
    int m0 = blockIdx.x * 32, b0 = blockIdx.y * 32;
    int tx = threadIdx.x, ty = threadIdx.y;
    if (blockIdx.x == 0 && blockIdx.y == 0) {
        int tid = ty * 32 + tx;
#pragma unroll
        for (int it = 0; it < 2; ++it) {
            int b = tid + it * 256;
            g_x[0][b] = x0[b];
            g_x[0][BB + b] = x1[b];
        }
    }
#pragma unroll
    for (int j = 0; j < 32; j += 8) {
        size_t a = (size_t)(m0 + ty + j) * BB + b0 + tx;
        float v = h0[a];
        traj0h[a] = v;
        t[ty + j][tx] = v;
    }
    __syncthreads();
    // zh partial: thread (tx,ty) sums rows ty*4..ty*4+3
    {
        float s = 0.f;
#pragma unroll
        for (int i = 0; i < 4; ++i) {
            int r = ty * 4 + i;
            s = fmaf(Z[m0 + r], t[r][tx], s);
        }
        zs[ty][tx] = s;
    }
#pragma unroll
    for (int j = 0; j < 32; j += 8) {
        float v = t[tx][ty + j];
        size_t o = (size_t)(b0 + ty + j) * NN + m0 + tx;
        __nv_bfloat16 hi = __float2bfloat16(v);
        g_Bhi[0][o] = hi;
        g_Blo[0][o] = __float2bfloat16(v - __bfloat162float(hi));
    }
    __syncthreads();
    if (ty == 0) {
        float s = 0.f;
#pragma unroll
        for (int r = 0; r < 8; ++r) s += zs[r][tx];
        atomicAdd(&g_zha[0][b0 + tx], s);
    }
}

// --------------------------------------------------------------------------
// Fused step kernel (see R4 comments). grid (4, 32), block 256.
// --------------------------------------------------------------------------
__device__ __forceinline__ void load_stage(uint32_t stg, int kt, int tid,
                                           int rowBase, int colBase,
                                           const __nv_bfloat16* Ah, const __nv_bfloat16* Al,
                                           const __nv_bfloat16* Bh, const __nv_bfloat16* Bl) {
#pragma unroll
    for (int i = 0; i < 8; ++i) {
        int ch = i * 256 + tid;          // 0..2047
        int tile = ch >> 9;              // 0..3
        int r = (ch >> 2) & 127;
        int c = ch & 3;
        const __nv_bfloat16* base = (tile == 0) ? Ah : (tile == 1) ? Al : (tile == 2) ? Bh : Bl;
        int rb = (tile < 2) ? rowBase : colBase;
        const char* src = (const char*)base + ((size_t)(rb + r) * NN + kt * BKt + c * 8) * 2;
        uint32_t dst = stg + tile * TILEB + r * ROWB + c * 16;
        cp16(dst, src);
    }
}

__device__ __forceinline__ void lds_frags(uint32_t stg, int ks,
                                          uint32_t aRow, uint32_t aK,
                                          uint32_t bRow, uint32_t bK,
                                          uint32_t* ah, uint32_t* al,
                                          uint32_t* bh, uint32_t* bl) {
#pragma unroll
    for (int mi = 0; mi < 4; ++mi) {
        uint32_t a = stg + (aRow + mi * 16) * ROWB + (aK + ks) * 2;
        ldsm4(ah + mi * 4, a);
        ldsm4(al + mi * 4, a + TILEB);
    }
#pragma unroll
    for (int ni = 0; ni < 4; ++ni) {
        uint32_t a = stg + 2 * TILEB + (bRow + ni * 8) * ROWB + (bK + ks) * 2;
        ldsm2(bh + ni * 2, a);
        ldsm2(bl + ni * 2, a + TILEB);
    }
}

__global__ void __launch_bounds__(256, 1) gemm_step_kernel(
    int p, int do_mma,
    const float* __restrict__ Mv,
    const float* __restrict__ Cc, const float* __restrict__ Amat,
    const float* __restrict__ Bm, const float* __restrict__ Z,
    float* __restrict__ trajh_next,   // traj_{t+1} h-block [NN][BB]
    float* __restrict__ trajx_cur,    // traj_t x-rows [2][BB]
    float* __restrict__ con_cur) {    // con_t [BB]
    extern __shared__ __align__(128) char smem[];
    uint32_t sb = smem_u32(smem);
    int tid = threadIdx.x;
    int lane = tid & 31;
    int wid = tid >> 5;
    int rowBase = blockIdx.y * BM;
    int colBase = blockIdx.x * BN;
    int q2 = p ^ 1;

    // ---- fused x-update (step t), designated block only ----
    if (blockIdx.x == 0 && blockIdx.y == 0) {
#pragma unroll
        for (int it = 0; it < 2; ++it) {
            int b = tid + it * 256;
            float zh = g_zha[p][b];
            g_zha[p][b] = 0.f;
            float xv0 = g_x[p][b], xv1 = g_x[p][BB + b];
            con_cur[b] = Bm[1] * zh;
            trajx_cur[b] = xv0;
            trajx_cur[BB + b] = xv1;
            g_x[q2][b] = Amat[0] * xv0 + Amat[1] * xv1 + Bm[0] * zh;
            g_x[q2][BB + b] = Amat[2] * xv0 + Amat[3] * xv1 + Bm[1] * zh;
        }
    }
    if (!do_mma) return;

    const __nv_bfloat16* Ah = g_Ahi;
    const __nv_bfloat16* Al = g_Alo;
    const __nv_bfloat16* Bh = g_Bhi[p];
    const __nv_bfloat16* Bl = g_Blo[p];

    // Warp tiling: 2 (M) x 4 (N) warps; warp tile 64x32
    int mb = (wid >> 2) * 64;
    int nb = (wid & 3) * 32;
    uint32_t aRow = (uint32_t)(mb + (lane & 15));
    uint32_t aK = (uint32_t)((lane >> 4) * 8);
    uint32_t bRow = (uint32_t)(nb + (lane & 7));
    uint32_t bK = (uint32_t)(((lane >> 3) & 1) * 8);

    float acc[4][4][4];
#pragma unroll
    for (int mi = 0; mi < 4; ++mi)
#pragma unroll
        for (int ni = 0; ni < 4; ++ni)
#pragma unroll
            for (int k = 0; k < 4; ++k) acc[mi][ni][k] = 0.f;

#pragma unroll
    for (int s = 0; s < NSTG; ++s) {
        load_stage(sb + s * STAGEB, s, tid, rowBase, colBase, Ah, Al, Bh, Bl);
        asm volatile("cp.async.commit_group;" ::: "memory");
    }

    for (int kt = 0; kt < NKT; ++kt) {
        asm volatile("cp.async.wait_group 3;" ::: "memory");
        __syncthreads();
        uint32_t stg = sb + (uint32_t)(kt % NSTG) * STAGEB;

        // Preload BOTH ks-groups' fragments, then run MMAs (ptxas interleaves).
        uint32_t ah[2][16], al2[2][16], bh2[2][8], bl2[2][8];
        lds_frags(stg, 0,  aRow, aK, bRow, bK, ah[0], al2[0], bh2[0], bl2[0]);
        lds_frags(stg, 16, aRow, aK, bRow, bK, ah[1], al2[1], bh2[1], bl2[1]);
#pragma unroll
        for (int g = 0; g < 2; ++g)
#pragma unroll
            for (int mi = 0; mi < 4; ++mi)
#pragma unroll
                for (int ni = 0; ni < 4; ++ni) {
                    mma_bf16(acc[mi][ni], &ah[g][mi * 4],  &bh2[g][ni * 2]);
                    mma_bf16(acc[mi][ni], &ah[g][mi * 4],  &bl2[g][ni * 2]);
                    mma_bf16(acc[mi][ni], &al2[g][mi * 4], &bh2[g][ni * 2]);
                }
        __syncthreads();
        if (kt + NSTG < NKT)
            load_stage(stg, kt + NSTG, tid, rowBase, colBase, Ah, Al, Bh, Bl);
        asm volatile("cp.async.commit_group;" ::: "memory");
    }
    __syncthreads();   // all smem reads done before Cst aliases the stages

    // ---- Epilogue pass 1: frags -> smem Cst [n][132] ----
    float* Cst = (float*)smem;
#pragma unroll
    for (int mi = 0; mi < 4; ++mi)
#pragma unroll
        for (int ni = 0; ni < 4; ++ni) {
            int m = mb + mi * 16 + (lane >> 2);
            int n = nb + ni * 8 + (lane & 3) * 2;
            Cst[n * 132 + m] = acc[mi][ni][0];
            Cst[(n + 1) * 132 + m] = acc[mi][ni][1];
            Cst[n * 132 + m + 8] = acc[mi][ni][2];
            Cst[(n + 1) * 132 + m + 8] = acc[mi][ni][3];
        }
    __syncthreads();

    // ---- Pass 2 (n-major): v = acc + DT*M*e; write Bhi/Blo, v->Cst, zh partial
    float CA0 = Cc[0] * Amat[0] + Cc[1] * Amat[2];
    float CA1 = Cc[0] * Amat[1] + Cc[1] * Amat[3];
    {
        int n = tid >> 1;
        int m0 = (tid & 1) * 64;
        float e = CA0 * g_x[p][colBase + n] + CA1 * g_x[p][BB + colBase + n];
        __nv_bfloat16* __restrict__ Bhn = g_Bhi[q2];
        __nv_bfloat16* __restrict__ Bln = g_Blo[q2];
        size_t obase = (size_t)(colBase + n) * NN + rowBase;
        float zp = 0.f;
#pragma unroll
        for (int q = 0; q < 16; ++q) {
            int m = m0 + q * 4;
            float4 c = *(float4*)&Cst[n * 132 + m];
            float4 mv4 = *(const float4*)&Mv[rowBase + m];
            float4 z4 = *(const float4*)&Z[rowBase + m];
            float4 v;
            v.x = c.x + DTc * mv4.x * e;
            v.y = c.y + DTc * mv4.y * e;
            v.z = c.z + DTc * mv4.z * e;
            v.w = c.w + DTc * mv4.w * e;
            *(float4*)&Cst[n * 132 + m] = v;
            zp += z4.x * v.x + z4.y * v.y + z4.z * v.z + z4.w * v.w;
            union { __nv_bfloat16 h[4]; uint2 u; } ph, pl;
            const float* vp = &v.x;
#pragma unroll
            for (int j = 0; j < 4; ++j) {
                __nv_bfloat16 hi = __float2bfloat16(vp[j]);
                ph.h[j] = hi;
                pl.h[j] = __float2bfloat16(vp[j] - __bfloat162float(hi));
            }
            *(uint2*)&Bhn[obase + m] = ph.u;
            *(uint2*)&Bln[obase + m] = pl.u;
        }
        zp += __shfl_xor_sync(0xFFFFFFFFu, zp, 1);
        if ((tid & 1) == 0)
            atomicAdd(&g_zha[q2][colBase + n], zp);
    }
    __syncthreads();

    // ---- Pass 3 (m-major): traj_{t+1} h-block [m][b], b contiguous ----
    {
        int m = tid >> 1;
        int n0 = (tid & 1) * 64;
        size_t tb = (size_t)(rowBase + m) * BB + colBase + n0;
#pragma unroll
        for (int q = 0; q < 16; ++q) {
            float4 v;
            v.x = Cst[(n0 + q * 4 + 0) * 132 + m];
            v.y = Cst[(n0 + q * 4 + 1) * 132 + m];
            v.z = Cst[(n0 + q * 4 + 2) * 132 + m];
            v.w = Cst[(n0 + q * 4 + 3) * 132 + m];
            *(float4*)&trajh_next[tb + q * 4] = v;
        }
    }
}

// --------------------------------------------------------------------------
extern "C" void kernel_launch(void* const* d_in, const int* in_sizes, int n_in,
                              void* d_out, int out_size) {
    const float* x0 = (const float*)d_in[0];
    const float* x1 = (const float*)d_in[1];
    const float* h0 = (const float*)d_in[2];
    const float* A  = (const float*)d_in[3];
    const float* Bm = (const float*)d_in[4];
    const float* C  = (const float*)d_in[5];
    const float* Mv = (const float*)d_in[6];
    const float* Z  = (const float*)d_in[7];
    const float* U  = (const float*)d_in[8];
    const float* V  = (const float*)d_in[9];
    const float* W  = (const float*)d_in[10];

    long long per_step_full = (long long)BB * (NN + 2 + 1);
    int steps = (int)((long long)out_size / per_step_full);
    if ((long long)steps * per_step_full != (long long)out_size)
        steps = (int)((long long)out_size / ((long long)BB * (NN + 2)));

    float* out  = (float*)d_out;
    float* traj = out;
    float* con  = out + (size_t)steps * (NN + 2) * BB;

    cudaFuncSetAttribute(gemm_step_kernel,
                         cudaFuncAttributeMaxDynamicSharedMemorySize, SMEM_BYTES);

    build_split_kernel<<<dim3(NN / 4 / 256, NN), 256>>>(W, U, V, Mv, Z, C, Bm);
    init_all_kernel<<<dim3(NN / 32, BB / 32), dim3(32, 8)>>>(h0, x0, x1, Z, traj + 2 * BB);

    for (int t = 0; t < steps; ++t) {
        int p = t & 1;
        int do_mma = (t < steps - 1);
        float* traj_t = traj + (size_t)t * (NN + 2) * BB;
        float* trajh_next = traj + (size_t)(t + 1) * (NN + 2) * BB + 2 * BB;
        if (!do_mma) trajh_next = traj_t + 2 * BB;   // unused, keep in-bounds
        gemm_step_kernel<<<dim3(BB / BN, NN / BM), 256, SMEM_BYTES>>>(
            p, do_mma, Mv, C, A, Bm, Z,
            trajh_next, traj_t, con + (size_t)t * BB);
    }
}